// round 2
// baseline (speedup 1.0000x reference)
#include <cuda_runtime.h>
#include <math.h>

// Problem dims (fixed by setup_inputs)
#define T_TOK 2048
#define DIM   2048
#define NEXP  16
#define IDIM  1024
#define SIDIM 2048
#define TOPK  4

// GEMM tiling
#define BM 128
#define BN 64
#define BK 16
#define TM 8
#define TN 4
// threads per gemm block = (BM/TM)*(BN/TN) = 16*16 = 256

#define MAXROWS (T_TOK*TOPK + NEXP*BM)   // 10240 (worst-case padded grouped rows)
#define MAXTILES (MAXROWS/BM)            // 80

// -------- scratch (static device globals; allocation inside kernel_launch is banned) --------
__device__ float g_hbuf[(size_t)MAXROWS * IDIM];     // routed SwiGLU hidden  [padded rows, I]
__device__ float g_eout[(size_t)MAXROWS * DIM];      // routed expert outputs [padded rows, D]
__device__ float g_hshared[(size_t)T_TOK * SIDIM];   // shared-expert hidden
__device__ int   g_topidx[T_TOK*TOPK];
__device__ float g_topw[T_TOK*TOPK];
__device__ int   g_counts[NEXP];
__device__ int   g_fill[NEXP];
__device__ int   g_offsets[NEXP];
__device__ int   g_tile_expert[MAXTILES];
__device__ int   g_rowtok[MAXROWS];                  // grouped row -> token id (-1 = pad)
__device__ int   g_posmap[T_TOK*TOPK];               // (token,k) -> grouped row

__device__ __forceinline__ float4 ld4(const float* p) {
    return *reinterpret_cast<const float4*>(p);
}

// =============================== router ===============================
// One block per token: 16 warps, warp e computes logit e; thread 0 does
// softmax + bias-corrected top-4 (bias shift is a constant -> same ranking).
__global__ void router_kernel(const float* __restrict__ x,
                              const float* __restrict__ gw,
                              const float* __restrict__ gb)
{
    __shared__ float sx[DIM];
    __shared__ float slog[NEXP];
    const int t   = blockIdx.x;
    const int tid = threadIdx.x;           // 512 threads

    *reinterpret_cast<float4*>(&sx[tid*4]) = ld4(x + (long long)t*DIM + tid*4);
    __syncthreads();

    const int w = tid >> 5, lane = tid & 31;
    const float* gwr = gw + w*DIM;
    float s = 0.f;
    for (int i = lane*4; i < DIM; i += 32*4) {
        float4 xv = *reinterpret_cast<float4*>(&sx[i]);
        float4 gv = ld4(gwr + i);
        s += xv.x*gv.x + xv.y*gv.y + xv.z*gv.z + xv.w*gv.w;
    }
    #pragma unroll
    for (int o = 16; o; o >>= 1) s += __shfl_down_sync(0xffffffffu, s, o);
    if (lane == 0) slog[w] = s;
    __syncthreads();

    if (tid == 0) {
        float p[NEXP], mx = -1e30f;
        #pragma unroll
        for (int e = 0; e < NEXP; e++) mx = fmaxf(mx, slog[e]);
        float sum = 0.f;
        #pragma unroll
        for (int e = 0; e < NEXP; e++) { p[e] = expf(slog[e] - mx); sum += p[e]; }
        const float inv = 1.f / sum;
        float score[NEXP];
        #pragma unroll
        for (int e = 0; e < NEXP; e++) { p[e] *= inv; score[e] = p[e] + gb[e]; }

        int sel[TOPK]; float wsum = 0.f;
        #pragma unroll
        for (int k = 0; k < TOPK; k++) {
            int best = 0; float bv = -1e30f;
            #pragma unroll
            for (int e = 0; e < NEXP; e++)
                if (score[e] > bv) { bv = score[e]; best = e; }   // strict > : lowest idx on tie
            sel[k] = best; score[best] = -1e31f; wsum += p[best];
        }
        const float invw = 1.f / wsum;
        #pragma unroll
        for (int k = 0; k < TOPK; k++) {
            g_topidx[t*TOPK + k] = sel[k];
            g_topw [t*TOPK + k] = p[sel[k]] * invw;
            atomicAdd(&g_counts[sel[k]], 1);
        }
    }
}

// =============================== scheduling ===============================
__global__ void zero_meta()
{
    int i = threadIdx.x;
    if (i < NEXP) { g_counts[i] = 0; g_fill[i] = 0; }
}

__global__ void sched_kernel()
{
    const int tid = threadIdx.x;   // 256
    if (tid == 0) {
        int base = 0;
        for (int e = 0; e < NEXP; e++) {
            g_offsets[e] = base;
            int nt = (g_counts[e] + BM - 1) / BM;
            int t0 = base / BM;
            for (int j = 0; j < nt; j++) g_tile_expert[t0 + j] = e;
            base += nt * BM;
        }
        for (int tl = base / BM; tl < MAXTILES; tl++) g_tile_expert[tl] = -1;
    }
    for (int i = tid; i < MAXROWS; i += blockDim.x) g_rowtok[i] = -1;
}

__global__ void scatter_kernel()
{
    const int p = blockIdx.x * blockDim.x + threadIdx.x;
    if (p >= T_TOK*TOPK) return;
    const int e = g_topidx[p];
    const int r = atomicAdd(&g_fill[e], 1);
    const int pos = g_offsets[e] + r;
    g_rowtok[pos] = p >> 2;   // token id
    g_posmap[p]   = pos;
}

// =============================== GEMM ===============================
// C[M,N] = A[M,K] @ B[K,N]   (row-major everywhere)
// GLU:    B is [K, 2N]; output = silu(A@B[:, :N]) * (A@B[:, N:2N])
// GATHER: A row m is X[rowtok[m], :]  (rowtok<0 -> zeros)
// tile_expert: per row-tile expert id (-1 -> inactive tile); B += e*bstride
template<bool GLU, bool GATHER>
__global__ __launch_bounds__(256, 2)
void gemm_tiled(const float* __restrict__ A,
                const float* __restrict__ Bbase,
                float* __restrict__ C,
                int K, int N, int lda, int ldb, int ldc,
                const int* __restrict__ rowtok,
                const int* __restrict__ tile_expert,
                long long bstride)
{
    const float* B = Bbase;
    if (tile_expert) {
        int e = tile_expert[blockIdx.y];
        if (e < 0) return;
        B += (long long)e * bstride;
    }

    __shared__ float As[BK][BM];
    __shared__ float Bs[BK][BN];
    __shared__ float Bs2[BK][BN];

    const int tid = threadIdx.x;
    const int tx  = tid & 15;       // output col group
    const int ty  = tid >> 4;       // output row group
    const int m0  = blockIdx.y * BM;
    const int n0  = blockIdx.x * BN;

    // A-tile loader mapping: each thread loads 8 consecutive K-floats of one row
    const int ar = tid >> 1;            // 0..127
    const int ac = (tid & 1) * 8;       // 0 or 8
    const float* arow;
    if (GATHER) {
        int tok = rowtok[m0 + ar];
        arow = (tok >= 0) ? (A + (long long)tok * lda) : nullptr;
    } else {
        arow = A + (long long)(m0 + ar) * lda;
    }
    // B-tile loader mapping: one float4 per thread
    const int brr = tid >> 4;           // 0..15
    const int bcc = (tid & 15) * 4;     // 0..60

    float acc[TM][TN], acc2[TM][TN];
    #pragma unroll
    for (int i = 0; i < TM; i++)
        #pragma unroll
        for (int j = 0; j < TN; j++) { acc[i][j] = 0.f; acc2[i][j] = 0.f; }

    for (int kt = 0; kt < K; kt += BK) {
        float4 a0, a1;
        if (!GATHER || arow) {
            a0 = ld4(arow + kt + ac);
            a1 = ld4(arow + kt + ac + 4);
        } else {
            a0 = make_float4(0.f,0.f,0.f,0.f); a1 = a0;
        }
        As[ac+0][ar] = a0.x; As[ac+1][ar] = a0.y; As[ac+2][ar] = a0.z; As[ac+3][ar] = a0.w;
        As[ac+4][ar] = a1.x; As[ac+5][ar] = a1.y; As[ac+6][ar] = a1.z; As[ac+7][ar] = a1.w;

        const float* bp = B + (long long)(kt + brr) * ldb + n0 + bcc;
        *reinterpret_cast<float4*>(&Bs[brr][bcc]) = ld4(bp);
        if (GLU)
            *reinterpret_cast<float4*>(&Bs2[brr][bcc]) = ld4(bp + N);
        __syncthreads();

        #pragma unroll
        for (int k = 0; k < BK; k++) {
            float a[TM], b[TN], b2[TN];
            #pragma unroll
            for (int i = 0; i < TM; i++) a[i] = As[k][ty*TM + i];
            #pragma unroll
            for (int j = 0; j < TN; j++) b[j] = Bs[k][tx*TN + j];
            if (GLU) {
                #pragma unroll
                for (int j = 0; j < TN; j++) b2[j] = Bs2[k][tx*TN + j];
            }
            #pragma unroll
            for (int i = 0; i < TM; i++)
                #pragma unroll
                for (int j = 0; j < TN; j++) {
                    acc[i][j] = fmaf(a[i], b[j], acc[i][j]);
                    if (GLU) acc2[i][j] = fmaf(a[i], b2[j], acc2[i][j]);
                }
        }
        __syncthreads();
    }

    #pragma unroll
    for (int i = 0; i < TM; i++) {
        const long long row = m0 + ty*TM + i;
        float* crow = C + row * (long long)ldc + n0 + tx*TN;
        #pragma unroll
        for (int j = 0; j < TN; j++) {
            float v;
            if (GLU) {
                float g = acc[i][j], u = acc2[i][j];
                v = (g / (1.f + expf(-g))) * u;     // silu(g)*u
            } else {
                v = acc[i][j];
            }
            crow[j] = v;
        }
    }
}

// =============================== combine ===============================
// out[t,:] (already holds shared-expert output) += sum_k w[t,k] * eout[pos[t,k], :]
__global__ void combine_kernel(float* __restrict__ out)
{
    const int t = blockIdx.x;
    __shared__ int   spos[TOPK];
    __shared__ float sw[TOPK];
    if (threadIdx.x < TOPK) {
        spos[threadIdx.x] = g_posmap[t*TOPK + threadIdx.x];
        sw[threadIdx.x]   = g_topw [t*TOPK + threadIdx.x];
    }
    __syncthreads();
    for (int d = threadIdx.x*4; d < DIM; d += blockDim.x*4) {
        float4 a = ld4(out + (long long)t*DIM + d);
        #pragma unroll
        for (int k = 0; k < TOPK; k++) {
            const float4 ev = ld4(g_eout + (long long)spos[k]*DIM + d);
            const float wk = sw[k];
            a.x = fmaf(wk, ev.x, a.x); a.y = fmaf(wk, ev.y, a.y);
            a.z = fmaf(wk, ev.z, a.z); a.w = fmaf(wk, ev.w, a.w);
        }
        *reinterpret_cast<float4*>(out + (long long)t*DIM + d) = a;
    }
}

// =============================== launch ===============================
extern "C" void kernel_launch(void* const* d_in, const int* in_sizes, int n_in,
                              void* d_out, int out_size)
{
    const float* x    = (const float*)d_in[0];   // [T, D]
    const float* gw   = (const float*)d_in[1];   // [E, D]
    const float* gb   = (const float*)d_in[2];   // [E]
    const float* wgu  = (const float*)d_in[3];   // [E, D, 2I]
    const float* wd   = (const float*)d_in[4];   // [E, I, D]
    const float* wsgu = (const float*)d_in[5];   // [D, 2*SI]
    const float* wsd  = (const float*)d_in[6];   // [SI, D]
    float* out = (float*)d_out;                  // [T, D]

    float *hbuf, *eout, *hsh;
    int *rowtok, *tilee;
    cudaGetSymbolAddress((void**)&hbuf,   g_hbuf);
    cudaGetSymbolAddress((void**)&eout,   g_eout);
    cudaGetSymbolAddress((void**)&hsh,    g_hshared);
    cudaGetSymbolAddress((void**)&rowtok, g_rowtok);
    cudaGetSymbolAddress((void**)&tilee,  g_tile_expert);

    zero_meta<<<1, 32>>>();
    router_kernel<<<T_TOK, 512>>>(x, gw, gb);
    sched_kernel<<<1, 256>>>();
    scatter_kernel<<<(T_TOK*TOPK + 255)/256, 256>>>();

    // routed gate_up + swiglu:  hbuf[m, :I] = silu(xg @ Wg) * (xg @ Wu)
    gemm_tiled<true, true><<<dim3(IDIM/BN, MAXTILES), 256>>>(
        x, wgu, hbuf, DIM, IDIM, DIM, 2*IDIM, IDIM,
        rowtok, tilee, (long long)DIM * 2 * IDIM);

    // routed down:  eout[m, :D] = hbuf @ Wd[e]
    gemm_tiled<false, false><<<dim3(DIM/BN, MAXTILES), 256>>>(
        hbuf, wd, eout, IDIM, DIM, IDIM, DIM, DIM,
        nullptr, tilee, (long long)IDIM * DIM);

    // shared gate_up + swiglu
    gemm_tiled<true, false><<<dim3(SIDIM/BN, T_TOK/BM), 256>>>(
        x, wsgu, hsh, DIM, SIDIM, DIM, 2*SIDIM, SIDIM,
        nullptr, nullptr, 0);

    // shared down -> writes d_out (every element)
    gemm_tiled<false, false><<<dim3(DIM/BN, T_TOK/BM), 256>>>(
        hsh, wsd, out, SIDIM, DIM, SIDIM, DIM, DIM,
        nullptr, nullptr, 0);

    // out += sum_k w * expert_out
    combine_kernel<<<T_TOK, 256>>>(out);
}

// round 7
// speedup vs baseline: 3.2483x; 3.2483x over previous
#include <cuda_runtime.h>
#include <cuda.h>
#include <cuda_bf16.h>
#include <math.h>
#include <stdint.h>

// Problem dims (fixed by setup_inputs)
#define T_TOK 2048
#define DIM   2048
#define NEXP  16
#define IDIM  1024
#define SIDIM 2048
#define TOPK  4

#define BM 128
#define MAXROWS (T_TOK*TOPK + NEXP*BM)   // 10240
#define MAXTILES (MAXROWS/BM)            // 80

// ======================= scratch (device globals) =======================
__device__ __nv_bfloat16 g_xh[(size_t)T_TOK*DIM];
__device__ __nv_bfloat16 g_xl[(size_t)T_TOK*DIM];
__device__ __nv_bfloat16 g_agh[(size_t)MAXROWS*DIM];
__device__ __nv_bfloat16 g_agl[(size_t)MAXROWS*DIM];
__device__ __nv_bfloat16 g_wguT_h[(size_t)NEXP*2*IDIM*DIM];
__device__ __nv_bfloat16 g_wguT_l[(size_t)NEXP*2*IDIM*DIM];
__device__ __nv_bfloat16 g_wdT_h[(size_t)NEXP*DIM*IDIM];
__device__ __nv_bfloat16 g_wdT_l[(size_t)NEXP*DIM*IDIM];
__device__ __nv_bfloat16 g_wsguT_h[(size_t)2*SIDIM*DIM];
__device__ __nv_bfloat16 g_wsguT_l[(size_t)2*SIDIM*DIM];
__device__ __nv_bfloat16 g_wsdT_h[(size_t)DIM*SIDIM];
__device__ __nv_bfloat16 g_wsdT_l[(size_t)DIM*SIDIM];
__device__ float g_gu[(size_t)MAXROWS*2*IDIM];
__device__ float g_gus[(size_t)T_TOK*2*SIDIM];
__device__ __nv_bfloat16 g_hbh[(size_t)MAXROWS*IDIM];
__device__ __nv_bfloat16 g_hbl[(size_t)MAXROWS*IDIM];
__device__ __nv_bfloat16 g_hsh_h[(size_t)T_TOK*SIDIM];
__device__ __nv_bfloat16 g_hsh_l[(size_t)T_TOK*SIDIM];
__device__ float g_eout[(size_t)MAXROWS*DIM];

__device__ int   g_topidx[T_TOK*TOPK];
__device__ float g_topw[T_TOK*TOPK];
__device__ int   g_counts[NEXP];
__device__ int   g_fill[NEXP];
__device__ int   g_offsets[NEXP];
__device__ int   g_tile_expert[MAXTILES];
__device__ int   g_rowtok[MAXROWS];
__device__ int   g_posmap[T_TOK*TOPK];

__device__ __forceinline__ float4 ld4(const float* p) {
    return *reinterpret_cast<const float4*>(p);
}

__device__ __forceinline__ uint32_t smem_to_u32(const void* smem_ptr) {
    uint32_t addr;
    asm("{ .reg .u64 tmp; cvta.to.shared.u64 tmp, %1; cvt.u32.u64 %0, tmp; }"
        : "=r"(addr) : "l"(smem_ptr));
    return addr;
}

// ======================= router / scheduling =======================
__global__ void router_kernel(const float* __restrict__ x,
                              const float* __restrict__ gw,
                              const float* __restrict__ gb)
{
    __shared__ float sx[DIM];
    __shared__ float slog[NEXP];
    const int t   = blockIdx.x;
    const int tid = threadIdx.x;           // 512 threads

    *reinterpret_cast<float4*>(&sx[tid*4]) = ld4(x + (long long)t*DIM + tid*4);
    __syncthreads();

    const int w = tid >> 5, lane = tid & 31;
    const float* gwr = gw + w*DIM;
    float s = 0.f;
    for (int i = lane*4; i < DIM; i += 32*4) {
        float4 xv = *reinterpret_cast<float4*>(&sx[i]);
        float4 gv = ld4(gwr + i);
        s += xv.x*gv.x + xv.y*gv.y + xv.z*gv.z + xv.w*gv.w;
    }
    #pragma unroll
    for (int o = 16; o; o >>= 1) s += __shfl_down_sync(0xffffffffu, s, o);
    if (lane == 0) slog[w] = s;
    __syncthreads();

    if (tid == 0) {
        float p[NEXP], mx = -1e30f;
        #pragma unroll
        for (int e = 0; e < NEXP; e++) mx = fmaxf(mx, slog[e]);
        float sum = 0.f;
        #pragma unroll
        for (int e = 0; e < NEXP; e++) { p[e] = expf(slog[e] - mx); sum += p[e]; }
        const float inv = 1.f / sum;
        float score[NEXP];
        #pragma unroll
        for (int e = 0; e < NEXP; e++) { p[e] *= inv; score[e] = p[e] + gb[e]; }

        int sel[TOPK]; float wsum = 0.f;
        #pragma unroll
        for (int k = 0; k < TOPK; k++) {
            int best = 0; float bv = -1e30f;
            #pragma unroll
            for (int e = 0; e < NEXP; e++)
                if (score[e] > bv) { bv = score[e]; best = e; }
            sel[k] = best; score[best] = -1e31f; wsum += p[best];
        }
        const float invw = 1.f / wsum;
        #pragma unroll
        for (int k = 0; k < TOPK; k++) {
            g_topidx[t*TOPK + k] = sel[k];
            g_topw [t*TOPK + k] = p[sel[k]] * invw;
            atomicAdd(&g_counts[sel[k]], 1);
        }
    }
}

__global__ void zero_meta()
{
    int i = threadIdx.x;
    if (i < NEXP) { g_counts[i] = 0; g_fill[i] = 0; }
}

__global__ void sched_kernel()
{
    const int tid = threadIdx.x;
    if (tid == 0) {
        int base = 0;
        for (int e = 0; e < NEXP; e++) {
            g_offsets[e] = base;
            int nt = (g_counts[e] + BM - 1) / BM;
            int t0 = base / BM;
            for (int j = 0; j < nt; j++) g_tile_expert[t0 + j] = e;
            base += nt * BM;
        }
        for (int tl = base / BM; tl < MAXTILES; tl++) g_tile_expert[tl] = -1;
    }
    for (int i = tid; i < MAXROWS; i += blockDim.x) g_rowtok[i] = -1;
}

__global__ void scatter_kernel()
{
    const int p = blockIdx.x * blockDim.x + threadIdx.x;
    if (p >= T_TOK*TOPK) return;
    const int e = g_topidx[p];
    const int r = atomicAdd(&g_fill[e], 1);
    const int pos = g_offsets[e] + r;
    g_rowtok[pos] = p >> 2;
    g_posmap[p]   = pos;
}

// ======================= conversion kernels =======================
__device__ __forceinline__ void split_bf16(float v, __nv_bfloat16& hi, __nv_bfloat16& lo) {
    hi = __float2bfloat16(v);
    lo = __float2bfloat16(v - __bfloat162float(hi));
}

__global__ void convert_x_kernel(const float* __restrict__ src,
                                 __nv_bfloat16* __restrict__ dh,
                                 __nv_bfloat16* __restrict__ dl, long long n4)
{
    long long p = (long long)blockIdx.x * blockDim.x + threadIdx.x;
    if (p >= n4) return;
    float4 v = ld4(src + p*4);
    union { __nv_bfloat16 b[4]; unsigned long long u; } H, L;
    split_bf16(v.x, H.b[0], L.b[0]);
    split_bf16(v.y, H.b[1], L.b[1]);
    split_bf16(v.z, H.b[2], L.b[2]);
    split_bf16(v.w, H.b[3], L.b[3]);
    *reinterpret_cast<unsigned long long*>(dh + p*4) = H.u;
    *reinterpret_cast<unsigned long long*>(dl + p*4) = L.u;
}

__global__ void gather_rows(const __nv_bfloat16* __restrict__ xh,
                            const __nv_bfloat16* __restrict__ xl,
                            __nv_bfloat16* __restrict__ agh,
                            __nv_bfloat16* __restrict__ agl)
{
    const int row = blockIdx.x;
    const int tid = threadIdx.x;   // 256 threads; DIM*2B = 4KB = 256x16B
    const int tok = g_rowtok[row];
    uint4* dh = reinterpret_cast<uint4*>(agh + (long long)row*DIM);
    uint4* dl = reinterpret_cast<uint4*>(agl + (long long)row*DIM);
    if (tok >= 0) {
        const uint4* sh = reinterpret_cast<const uint4*>(xh + (long long)tok*DIM);
        const uint4* sl = reinterpret_cast<const uint4*>(xl + (long long)tok*DIM);
        dh[tid] = sh[tid];
        dl[tid] = sl[tid];
    } else {
        uint4 z = make_uint4(0,0,0,0);
        dh[tid] = z; dl[tid] = z;
    }
}

// fp32 src [E][R][C] -> bf16 hi/lo dst [E][C][R]  (transpose + split)
__global__ void transpose_convert(const float* __restrict__ src,
                                  __nv_bfloat16* __restrict__ dh,
                                  __nv_bfloat16* __restrict__ dl,
                                  int R, int C)
{
    __shared__ float t[32][33];
    const int e  = blockIdx.z;
    const int c0 = blockIdx.x * 32;
    const int r0 = blockIdx.y * 32;
    const int tx = threadIdx.x, ty = threadIdx.y;   // (32, 8)
    const float* s = src + (long long)e*R*C;
    #pragma unroll
    for (int j = 0; j < 32; j += 8)
        t[ty+j][tx] = s[(long long)(r0+ty+j)*C + c0+tx];
    __syncthreads();
    __nv_bfloat16* oh = dh + (long long)e*C*R;
    __nv_bfloat16* ol = dl + (long long)e*C*R;
    #pragma unroll
    for (int j = 0; j < 32; j += 8) {
        float v = t[tx][ty+j];
        __nv_bfloat16 hi, lo; split_bf16(v, hi, lo);
        long long di = (long long)(c0+ty+j)*R + r0+tx;
        oh[di] = hi; ol[di] = lo;
    }
}

// gu fp32 [rows, 2I] -> h = silu(g)*u -> bf16 hi/lo [rows, I]
__global__ void swiglu_convert(const float* __restrict__ gu,
                               __nv_bfloat16* __restrict__ hh,
                               __nv_bfloat16* __restrict__ hl,
                               int I, long long total4)
{
    long long p = (long long)blockIdx.x * blockDim.x + threadIdx.x;
    if (p >= total4) return;
    const int per = I / 4;
    long long r = p / per;
    int i4 = (int)(p % per) * 4;
    const float* base = gu + r * (long long)(2*I);
    float4 g = ld4(base + i4);
    float4 u = ld4(base + I + i4);
    float h0 = (g.x / (1.f + expf(-g.x))) * u.x;
    float h1 = (g.y / (1.f + expf(-g.y))) * u.y;
    float h2 = (g.z / (1.f + expf(-g.z))) * u.z;
    float h3 = (g.w / (1.f + expf(-g.w))) * u.w;
    union { __nv_bfloat16 b[4]; unsigned long long v; } H, L;
    split_bf16(h0, H.b[0], L.b[0]);
    split_bf16(h1, H.b[1], L.b[1]);
    split_bf16(h2, H.b[2], L.b[2]);
    split_bf16(h3, H.b[3], L.b[3]);
    *reinterpret_cast<unsigned long long*>(hh + r*(long long)I + i4) = H.v;
    *reinterpret_cast<unsigned long long*>(hl + r*(long long)I + i4) = L.v;
}

// ======================= mma.sync GEMM =======================
// C tile 128x64. A [M,K] row-major, B [N,K] row-major (both K-contig), bf16 hi/lo.
// bf16x3 split: C = Ah*Bh + Ah*Bl + Al*Bh  (fp32 register accum)
// 256 threads = 8 warps (4 M x 2 N); warp tile 32x32; mma m16n8k16.
// Static smem only: 2 stages x 24KB = 48KB, XOR-swizzled 64B rows.

#define SWZ(r, cb) ((uint32_t)(r)*64u + ((uint32_t)(((cb) ^ ((r) & 3))) << 4))
#define SA_H 0
#define SA_L 8192
#define SB_H 16384
#define SB_L 20480
#define STG  24576

__device__ __forceinline__ void cp16(uint32_t d, const void* s) {
    asm volatile("cp.async.cg.shared.global [%0], [%1], 16;\n" :: "r"(d), "l"(s));
}
__device__ __forceinline__ void ldm4(uint32_t* r, uint32_t a) {
    asm volatile("ldmatrix.sync.aligned.m8n8.x4.shared.b16 {%0,%1,%2,%3}, [%4];\n"
        : "=r"(r[0]), "=r"(r[1]), "=r"(r[2]), "=r"(r[3]) : "r"(a));
}
__device__ __forceinline__ void mma16816(float* c, const uint32_t* a, uint32_t b0, uint32_t b1) {
    asm volatile("mma.sync.aligned.m16n8k16.row.col.f32.bf16.bf16.f32 "
        "{%0,%1,%2,%3}, {%4,%5,%6,%7}, {%8,%9}, {%0,%1,%2,%3};\n"
        : "+f"(c[0]), "+f"(c[1]), "+f"(c[2]), "+f"(c[3])
        : "r"(a[0]), "r"(a[1]), "r"(a[2]), "r"(a[3]), "r"(b0), "r"(b1));
}

__device__ __forceinline__ void load_stage(uint32_t st,
    const __nv_bfloat16* __restrict__ Ah, const __nv_bfloat16* __restrict__ Al,
    const __nv_bfloat16* __restrict__ Bh, const __nv_bfloat16* __restrict__ Bl,
    int am0, int bn0, int ldk, int k0, int tid)
{
    // A tiles: 128 rows x 4 chunks (16B) each
    #pragma unroll
    for (int i = 0; i < 2; i++) {
        const int idx = tid + i*256;
        const int row = idx >> 2, cb = idx & 3;
        const uint32_t so = SWZ(row, cb);
        const size_t ga = (size_t)(am0+row)*ldk + k0 + cb*8;
        cp16(st + SA_H + so, Ah + ga);
        cp16(st + SA_L + so, Al + ga);
    }
    // B tiles: 64 rows x 4 chunks
    {
        const int row = tid >> 2, cb = tid & 3;
        const uint32_t so = SWZ(row, cb);
        const size_t gb = (size_t)(bn0+row)*ldk + k0 + cb*8;
        cp16(st + SB_H + so, Bh + gb);
        cp16(st + SB_L + so, Bl + gb);
    }
}

__global__ void __launch_bounds__(256, 2) gemm_mma(
    const __nv_bfloat16* __restrict__ Ah, const __nv_bfloat16* __restrict__ Al,
    const __nv_bfloat16* __restrict__ Bh, const __nv_bfloat16* __restrict__ Bl,
    float* __restrict__ C, int K, int ldc,
    const int* __restrict__ tile_expert, int bNrows)
{
    __shared__ char smem[2*STG];    // 49152 bytes (static limit)
    const uint32_t sb = smem_to_u32(smem);

    int e = 0;
    if (tile_expert) { e = tile_expert[blockIdx.y]; if (e < 0) return; }
    const int m0 = blockIdx.y * 128;
    const int n0 = blockIdx.x * 64;
    const int brow0 = e * bNrows + n0;

    const int tid = threadIdx.x, lane = tid & 31, wid = tid >> 5;
    const int wm = wid >> 1, wn = wid & 1;        // 4 M x 2 N warps

    const int nk = K / 32;

    // prologue
    load_stage(sb, Ah, Al, Bh, Bl, m0, brow0, K, 0, tid);
    asm volatile("cp.async.commit_group;\n");

    float acc[2][4][4];
    #pragma unroll
    for (int a = 0; a < 2; a++)
        #pragma unroll
        for (int b = 0; b < 4; b++)
            #pragma unroll
            for (int c = 0; c < 4; c++) acc[a][b][c] = 0.f;

    for (int kt = 0; kt < nk; kt++) {
        if (kt + 1 < nk) {
            load_stage(sb + ((kt+1)&1)*STG, Ah, Al, Bh, Bl, m0, brow0, K, (kt+1)*32, tid);
            asm volatile("cp.async.commit_group;\n");
            asm volatile("cp.async.wait_group 1;\n");
        } else {
            asm volatile("cp.async.wait_group 0;\n");
        }
        __syncthreads();

        const uint32_t Ab = sb + (kt & 1)*STG;

        #pragma unroll
        for (int kh = 0; kh < 2; kh++) {
            uint32_t fah[2][4], fal[2][4], fbh[2][4], fbl[2][4];
            const int ar  = wm*32 + (lane & 15);
            const int acb = kh*2 + (lane >> 4);
            #pragma unroll
            for (int mt = 0; mt < 2; mt++) {
                ldm4(fah[mt], Ab + SA_H + SWZ(ar + mt*16, acb));
                ldm4(fal[mt], Ab + SA_L + SWZ(ar + mt*16, acb));
            }
            const int br  = wn*32 + (lane & 7) + ((lane >> 4) << 3);
            const int bcb = kh*2 + ((lane >> 3) & 1);
            #pragma unroll
            for (int np = 0; np < 2; np++) {
                ldm4(fbh[np], Ab + SB_H + SWZ(br + np*16, bcb));
                ldm4(fbl[np], Ab + SB_L + SWZ(br + np*16, bcb));
            }
            #pragma unroll
            for (int mt = 0; mt < 2; mt++)
                #pragma unroll
                for (int nt = 0; nt < 4; nt++) {
                    const int np = nt >> 1, hx = (nt & 1)*2;
                    mma16816(acc[mt][nt], fah[mt], fbh[np][hx], fbh[np][hx+1]);
                    mma16816(acc[mt][nt], fah[mt], fbl[np][hx], fbl[np][hx+1]);
                    mma16816(acc[mt][nt], fal[mt], fbh[np][hx], fbh[np][hx+1]);
                }
        }
        __syncthreads();
    }

    // epilogue
    const int rbase = m0 + wm*32 + (lane >> 2);
    const int cbase = n0 + wn*32 + (lane & 3)*2;
    #pragma unroll
    for (int mt = 0; mt < 2; mt++)
        #pragma unroll
        for (int nt = 0; nt < 4; nt++) {
            const long long r0 = rbase + mt*16;
            const int c0 = cbase + nt*8;
            *reinterpret_cast<float2*>(C + r0*ldc + c0) =
                make_float2(acc[mt][nt][0], acc[mt][nt][1]);
            *reinterpret_cast<float2*>(C + (r0+8)*ldc + c0) =
                make_float2(acc[mt][nt][2], acc[mt][nt][3]);
        }
}

// ======================= combine =======================
__global__ void combine_kernel(float* __restrict__ out)
{
    const int t = blockIdx.x;
    __shared__ int   spos[TOPK];
    __shared__ float sw[TOPK];
    if (threadIdx.x < TOPK) {
        spos[threadIdx.x] = g_posmap[t*TOPK + threadIdx.x];
        sw[threadIdx.x]   = g_topw [t*TOPK + threadIdx.x];
    }
    __syncthreads();
    for (int d = threadIdx.x*4; d < DIM; d += blockDim.x*4) {
        float4 a = ld4(out + (long long)t*DIM + d);
        #pragma unroll
        for (int k = 0; k < TOPK; k++) {
            const float4 ev = ld4(g_eout + (long long)spos[k]*DIM + d);
            const float wk = sw[k];
            a.x = fmaf(wk, ev.x, a.x); a.y = fmaf(wk, ev.y, a.y);
            a.z = fmaf(wk, ev.z, a.z); a.w = fmaf(wk, ev.w, a.w);
        }
        *reinterpret_cast<float4*>(out + (long long)t*DIM + d) = a;
    }
}

// ======================= host =======================
extern "C" void kernel_launch(void* const* d_in, const int* in_sizes, int n_in,
                              void* d_out, int out_size)
{
    const float* x    = (const float*)d_in[0];
    const float* gw   = (const float*)d_in[1];
    const float* gb   = (const float*)d_in[2];
    const float* wgu  = (const float*)d_in[3];
    const float* wd   = (const float*)d_in[4];
    const float* wsgu = (const float*)d_in[5];
    const float* wsd  = (const float*)d_in[6];
    float* out = (float*)d_out;

    void *xh, *xl, *agh, *agl, *wguTh, *wguTl, *wdTh, *wdTl,
         *wsguTh, *wsguTl, *wsdTh, *wsdTl, *gu, *gus, *hbh, *hbl,
         *hshh, *hshl, *eout, *tilee;
    cudaGetSymbolAddress(&xh, g_xh);       cudaGetSymbolAddress(&xl, g_xl);
    cudaGetSymbolAddress(&agh, g_agh);     cudaGetSymbolAddress(&agl, g_agl);
    cudaGetSymbolAddress(&wguTh, g_wguT_h);cudaGetSymbolAddress(&wguTl, g_wguT_l);
    cudaGetSymbolAddress(&wdTh, g_wdT_h);  cudaGetSymbolAddress(&wdTl, g_wdT_l);
    cudaGetSymbolAddress(&wsguTh, g_wsguT_h); cudaGetSymbolAddress(&wsguTl, g_wsguT_l);
    cudaGetSymbolAddress(&wsdTh, g_wsdT_h);   cudaGetSymbolAddress(&wsdTl, g_wsdT_l);
    cudaGetSymbolAddress(&gu, g_gu);       cudaGetSymbolAddress(&gus, g_gus);
    cudaGetSymbolAddress(&hbh, g_hbh);     cudaGetSymbolAddress(&hbl, g_hbl);
    cudaGetSymbolAddress(&hshh, g_hsh_h);  cudaGetSymbolAddress(&hshl, g_hsh_l);
    cudaGetSymbolAddress(&eout, g_eout);
    cudaGetSymbolAddress(&tilee, g_tile_expert);

    // --- routing ---
    zero_meta<<<1, 32>>>();
    router_kernel<<<T_TOK, 512>>>(x, gw, gb);
    sched_kernel<<<1, 256>>>();
    scatter_kernel<<<(T_TOK*TOPK + 255)/256, 256>>>();

    // --- conversions ---
    convert_x_kernel<<<(T_TOK*DIM/4 + 255)/256, 256>>>(
        x, (__nv_bfloat16*)xh, (__nv_bfloat16*)xl, (long long)T_TOK*DIM/4);
    gather_rows<<<MAXROWS, 256>>>((const __nv_bfloat16*)xh, (const __nv_bfloat16*)xl,
                                  (__nv_bfloat16*)agh, (__nv_bfloat16*)agl);
    transpose_convert<<<dim3(2*IDIM/32, DIM/32, NEXP), dim3(32,8)>>>(
        wgu, (__nv_bfloat16*)wguTh, (__nv_bfloat16*)wguTl, DIM, 2*IDIM);
    transpose_convert<<<dim3(DIM/32, IDIM/32, NEXP), dim3(32,8)>>>(
        wd, (__nv_bfloat16*)wdTh, (__nv_bfloat16*)wdTl, IDIM, DIM);
    transpose_convert<<<dim3(2*SIDIM/32, DIM/32, 1), dim3(32,8)>>>(
        wsgu, (__nv_bfloat16*)wsguTh, (__nv_bfloat16*)wsguTl, DIM, 2*SIDIM);
    transpose_convert<<<dim3(DIM/32, SIDIM/32, 1), dim3(32,8)>>>(
        wsd, (__nv_bfloat16*)wsdTh, (__nv_bfloat16*)wsdTl, SIDIM, DIM);

    // --- routed expert GEMMs ---
    gemm_mma<<<dim3(2*IDIM/64, MAXTILES), 256>>>(
        (const __nv_bfloat16*)agh, (const __nv_bfloat16*)agl,
        (const __nv_bfloat16*)wguTh, (const __nv_bfloat16*)wguTl,
        (float*)gu, DIM, 2*IDIM, (const int*)tilee, 2*IDIM);
    swiglu_convert<<<((long long)MAXROWS*IDIM/4 + 255)/256, 256>>>(
        (const float*)gu, (__nv_bfloat16*)hbh, (__nv_bfloat16*)hbl,
        IDIM, (long long)MAXROWS*IDIM/4);
    gemm_mma<<<dim3(DIM/64, MAXTILES), 256>>>(
        (const __nv_bfloat16*)hbh, (const __nv_bfloat16*)hbl,
        (const __nv_bfloat16*)wdTh, (const __nv_bfloat16*)wdTl,
        (float*)eout, IDIM, DIM, (const int*)tilee, DIM);

    // --- shared expert GEMMs ---
    gemm_mma<<<dim3(2*SIDIM/64, T_TOK/128), 256>>>(
        (const __nv_bfloat16*)xh, (const __nv_bfloat16*)xl,
        (const __nv_bfloat16*)wsguTh, (const __nv_bfloat16*)wsguTl,
        (float*)gus, DIM, 2*SIDIM, nullptr, 0);
    swiglu_convert<<<((long long)T_TOK*SIDIM/4 + 255)/256, 256>>>(
        (const float*)gus, (__nv_bfloat16*)hshh, (__nv_bfloat16*)hshl,
        SIDIM, (long long)T_TOK*SIDIM/4);
    gemm_mma<<<dim3(DIM/64, T_TOK/128), 256>>>(
        (const __nv_bfloat16*)hshh, (const __nv_bfloat16*)hshl,
        (const __nv_bfloat16*)wsdTh, (const __nv_bfloat16*)wsdTl,
        out, SIDIM, DIM, nullptr, 0);

    // --- combine ---
    combine_kernel<<<T_TOK, 256>>>(out);
}

// round 10
// speedup vs baseline: 4.0724x; 1.2537x over previous
#include <cuda_runtime.h>
#include <cuda.h>
#include <cuda_bf16.h>
#include <math.h>
#include <stdint.h>

// Problem dims (fixed by setup_inputs)
#define T_TOK 2048
#define DIM   2048
#define NEXP  16
#define IDIM  1024
#define SIDIM 2048
#define TOPK  4

#define BM 128
#define MAXROWS (T_TOK*TOPK + NEXP*BM)   // 10240
#define MAXTILES (MAXROWS/BM)            // 80

// ======================= scratch (device globals) =======================
__device__ __nv_bfloat16 g_xh[(size_t)T_TOK*DIM];
__device__ __nv_bfloat16 g_xl[(size_t)T_TOK*DIM];
__device__ __nv_bfloat16 g_agh[(size_t)MAXROWS*DIM];
__device__ __nv_bfloat16 g_agl[(size_t)MAXROWS*DIM];
__device__ __nv_bfloat16 g_wguT_h[(size_t)NEXP*2*IDIM*DIM];
__device__ __nv_bfloat16 g_wguT_l[(size_t)NEXP*2*IDIM*DIM];
__device__ __nv_bfloat16 g_wdT_h[(size_t)NEXP*DIM*IDIM];
__device__ __nv_bfloat16 g_wdT_l[(size_t)NEXP*DIM*IDIM];
__device__ __nv_bfloat16 g_wsguT_h[(size_t)2*SIDIM*DIM];
__device__ __nv_bfloat16 g_wsguT_l[(size_t)2*SIDIM*DIM];
__device__ __nv_bfloat16 g_wsdT_h[(size_t)DIM*SIDIM];
__device__ __nv_bfloat16 g_wsdT_l[(size_t)DIM*SIDIM];
__device__ float g_gu[(size_t)MAXROWS*2*IDIM];
__device__ float g_gus[(size_t)T_TOK*2*SIDIM];
__device__ __nv_bfloat16 g_hbh[(size_t)MAXROWS*IDIM];
__device__ __nv_bfloat16 g_hbl[(size_t)MAXROWS*IDIM];
__device__ __nv_bfloat16 g_hsh_h[(size_t)T_TOK*SIDIM];
__device__ __nv_bfloat16 g_hsh_l[(size_t)T_TOK*SIDIM];
__device__ float g_eout[(size_t)MAXROWS*DIM];

__device__ int   g_topidx[T_TOK*TOPK];
__device__ float g_topw[T_TOK*TOPK];
__device__ int   g_counts[NEXP];
__device__ int   g_fill[NEXP];
__device__ int   g_offsets[NEXP];
__device__ int   g_tile_expert[MAXTILES];
__device__ int   g_rowtok[MAXROWS];
__device__ int   g_posmap[T_TOK*TOPK];

__device__ __forceinline__ float4 ld4(const float* p) {
    return *reinterpret_cast<const float4*>(p);
}

__device__ __forceinline__ uint32_t smem_to_u32(const void* smem_ptr) {
    uint32_t addr;
    asm("{ .reg .u64 tmp; cvta.to.shared.u64 tmp, %1; cvt.u32.u64 %0, tmp; }"
        : "=r"(addr) : "l"(smem_ptr));
    return addr;
}

// ======================= router / scheduling =======================
__global__ void router_kernel(const float* __restrict__ x,
                              const float* __restrict__ gw,
                              const float* __restrict__ gb)
{
    __shared__ float sx[DIM];
    __shared__ float slog[NEXP];
    const int t   = blockIdx.x;
    const int tid = threadIdx.x;           // 512 threads

    *reinterpret_cast<float4*>(&sx[tid*4]) = ld4(x + (long long)t*DIM + tid*4);
    __syncthreads();

    const int w = tid >> 5, lane = tid & 31;
    const float* gwr = gw + w*DIM;
    float s = 0.f;
    for (int i = lane*4; i < DIM; i += 32*4) {
        float4 xv = *reinterpret_cast<float4*>(&sx[i]);
        float4 gv = ld4(gwr + i);
        s += xv.x*gv.x + xv.y*gv.y + xv.z*gv.z + xv.w*gv.w;
    }
    #pragma unroll
    for (int o = 16; o; o >>= 1) s += __shfl_down_sync(0xffffffffu, s, o);
    if (lane == 0) slog[w] = s;
    __syncthreads();

    if (tid == 0) {
        float p[NEXP], mx = -1e30f;
        #pragma unroll
        for (int e = 0; e < NEXP; e++) mx = fmaxf(mx, slog[e]);
        float sum = 0.f;
        #pragma unroll
        for (int e = 0; e < NEXP; e++) { p[e] = expf(slog[e] - mx); sum += p[e]; }
        const float inv = 1.f / sum;
        float score[NEXP];
        #pragma unroll
        for (int e = 0; e < NEXP; e++) { p[e] *= inv; score[e] = p[e] + gb[e]; }

        int sel[TOPK]; float wsum = 0.f;
        #pragma unroll
        for (int k = 0; k < TOPK; k++) {
            int best = 0; float bv = -1e30f;
            #pragma unroll
            for (int e = 0; e < NEXP; e++)
                if (score[e] > bv) { bv = score[e]; best = e; }
            sel[k] = best; score[best] = -1e31f; wsum += p[best];
        }
        const float invw = 1.f / wsum;
        #pragma unroll
        for (int k = 0; k < TOPK; k++) {
            g_topidx[t*TOPK + k] = sel[k];
            g_topw [t*TOPK + k] = p[sel[k]] * invw;
            atomicAdd(&g_counts[sel[k]], 1);
        }
    }
}

__global__ void zero_meta()
{
    int i = threadIdx.x;
    if (i < NEXP) { g_counts[i] = 0; g_fill[i] = 0; }
}

__global__ void sched_kernel()
{
    const int tid = threadIdx.x;
    if (tid == 0) {
        int base = 0;
        for (int e = 0; e < NEXP; e++) {
            g_offsets[e] = base;
            int nt = (g_counts[e] + BM - 1) / BM;
            int t0 = base / BM;
            for (int j = 0; j < nt; j++) g_tile_expert[t0 + j] = e;
            base += nt * BM;
        }
        for (int tl = base / BM; tl < MAXTILES; tl++) g_tile_expert[tl] = -1;
    }
    for (int i = tid; i < MAXROWS; i += blockDim.x) g_rowtok[i] = -1;
}

__global__ void scatter_kernel()
{
    const int p = blockIdx.x * blockDim.x + threadIdx.x;
    if (p >= T_TOK*TOPK) return;
    const int e = g_topidx[p];
    const int r = atomicAdd(&g_fill[e], 1);
    const int pos = g_offsets[e] + r;
    g_rowtok[pos] = p >> 2;
    g_posmap[p]   = pos;
}

// ======================= conversion kernels =======================
__device__ __forceinline__ void split_bf16(float v, __nv_bfloat16& hi, __nv_bfloat16& lo) {
    hi = __float2bfloat16(v);
    lo = __float2bfloat16(v - __bfloat162float(hi));
}

__global__ void convert_x_kernel(const float* __restrict__ src,
                                 __nv_bfloat16* __restrict__ dh,
                                 __nv_bfloat16* __restrict__ dl, long long n4)
{
    long long p = (long long)blockIdx.x * blockDim.x + threadIdx.x;
    if (p >= n4) return;
    float4 v = ld4(src + p*4);
    union { __nv_bfloat16 b[4]; unsigned long long u; } H, L;
    split_bf16(v.x, H.b[0], L.b[0]);
    split_bf16(v.y, H.b[1], L.b[1]);
    split_bf16(v.z, H.b[2], L.b[2]);
    split_bf16(v.w, H.b[3], L.b[3]);
    *reinterpret_cast<unsigned long long*>(dh + p*4) = H.u;
    *reinterpret_cast<unsigned long long*>(dl + p*4) = L.u;
}

__global__ void gather_rows(const __nv_bfloat16* __restrict__ xh,
                            const __nv_bfloat16* __restrict__ xl,
                            __nv_bfloat16* __restrict__ agh,
                            __nv_bfloat16* __restrict__ agl)
{
    const int row = blockIdx.x;
    const int tid = threadIdx.x;   // 256 threads; DIM*2B = 4KB = 256x16B
    const int tok = g_rowtok[row];
    uint4* dh = reinterpret_cast<uint4*>(agh + (long long)row*DIM);
    uint4* dl = reinterpret_cast<uint4*>(agl + (long long)row*DIM);
    if (tok >= 0) {
        const uint4* sh = reinterpret_cast<const uint4*>(xh + (long long)tok*DIM);
        const uint4* sl = reinterpret_cast<const uint4*>(xl + (long long)tok*DIM);
        dh[tid] = sh[tid];
        dl[tid] = sl[tid];
    } else {
        uint4 z = make_uint4(0,0,0,0);
        dh[tid] = z; dl[tid] = z;
    }
}

// fp32 src [E][R][C] -> bf16 hi/lo dst [E][C][R]  (transpose + split)
__global__ void transpose_convert(const float* __restrict__ src,
                                  __nv_bfloat16* __restrict__ dh,
                                  __nv_bfloat16* __restrict__ dl,
                                  int R, int C)
{
    __shared__ float t[32][33];
    const int e  = blockIdx.z;
    const int c0 = blockIdx.x * 32;
    const int r0 = blockIdx.y * 32;
    const int tx = threadIdx.x, ty = threadIdx.y;   // (32, 8)
    const float* s = src + (long long)e*R*C;
    #pragma unroll
    for (int j = 0; j < 32; j += 8)
        t[ty+j][tx] = s[(long long)(r0+ty+j)*C + c0+tx];
    __syncthreads();
    __nv_bfloat16* oh = dh + (long long)e*C*R;
    __nv_bfloat16* ol = dl + (long long)e*C*R;
    #pragma unroll
    for (int j = 0; j < 32; j += 8) {
        float v = t[tx][ty+j];
        __nv_bfloat16 hi, lo; split_bf16(v, hi, lo);
        long long di = (long long)(c0+ty+j)*R + r0+tx;
        oh[di] = hi; ol[di] = lo;
    }
}

// gu fp32 [rows, 2I] -> h = silu(g)*u -> bf16 hi/lo [rows, I]
__global__ void swiglu_convert(const float* __restrict__ gu,
                               __nv_bfloat16* __restrict__ hh,
                               __nv_bfloat16* __restrict__ hl,
                               int I, long long total4)
{
    long long p = (long long)blockIdx.x * blockDim.x + threadIdx.x;
    if (p >= total4) return;
    const int per = I / 4;
    long long r = p / per;
    int i4 = (int)(p % per) * 4;
    const float* base = gu + r * (long long)(2*I);
    float4 g = ld4(base + i4);
    float4 u = ld4(base + I + i4);
    float h0 = (g.x / (1.f + expf(-g.x))) * u.x;
    float h1 = (g.y / (1.f + expf(-g.y))) * u.y;
    float h2 = (g.z / (1.f + expf(-g.z))) * u.z;
    float h3 = (g.w / (1.f + expf(-g.w))) * u.w;
    union { __nv_bfloat16 b[4]; unsigned long long v; } H, L;
    split_bf16(h0, H.b[0], L.b[0]);
    split_bf16(h1, H.b[1], L.b[1]);
    split_bf16(h2, H.b[2], L.b[2]);
    split_bf16(h3, H.b[3], L.b[3]);
    *reinterpret_cast<unsigned long long*>(hh + r*(long long)I + i4) = H.v;
    *reinterpret_cast<unsigned long long*>(hl + r*(long long)I + i4) = L.v;
}

// ======================= mma.sync GEMM =======================
// C tile 128x128. A [M,K] row-major, B [N,K] row-major (both K-contig), bf16 hi/lo.
// bf16x3 split: C = Ah*Bh + Ah*Bl + Al*Bh  (fp32 register accum)
// 256 threads = 8 warps (2 M x 4 N); warp tile 64x32; mma m16n8k16; k-step 16.
// Smem stage = A[128 rows x 64B (hi|lo)] + B[128 x 64B] = 16KB; 3 stages = 48KB static.
// Swizzle c ^ ((r>>1)&3) over 16B chunks -> conflict-free ldmatrix phases.

#define SWZ64(r, c) ((uint32_t)(r)*64u + ((uint32_t)(((c) ^ (((r)>>1)&3))) << 4))
#define SB_OFF 8192
#define STG16  16384

__device__ __forceinline__ void cp16(uint32_t d, const void* s) {
    asm volatile("cp.async.cg.shared.global [%0], [%1], 16;\n" :: "r"(d), "l"(s));
}
__device__ __forceinline__ void ldm4(uint32_t* r, uint32_t a) {
    asm volatile("ldmatrix.sync.aligned.m8n8.x4.shared.b16 {%0,%1,%2,%3}, [%4];\n"
        : "=r"(r[0]), "=r"(r[1]), "=r"(r[2]), "=r"(r[3]) : "r"(a));
}
__device__ __forceinline__ void mma16816(float* c, const uint32_t* a, uint32_t b0, uint32_t b1) {
    asm volatile("mma.sync.aligned.m16n8k16.row.col.f32.bf16.bf16.f32 "
        "{%0,%1,%2,%3}, {%4,%5,%6,%7}, {%8,%9}, {%0,%1,%2,%3};\n"
        : "+f"(c[0]), "+f"(c[1]), "+f"(c[2]), "+f"(c[3])
        : "r"(a[0]), "r"(a[1]), "r"(a[2]), "r"(a[3]), "r"(b0), "r"(b1));
}

__device__ __forceinline__ void load_stage(uint32_t st,
    const __nv_bfloat16* __restrict__ Ah, const __nv_bfloat16* __restrict__ Al,
    const __nv_bfloat16* __restrict__ Bh, const __nv_bfloat16* __restrict__ Bl,
    int am0, int bn0, int ldk, int k0, int tid)
{
    const int row = tid >> 1;          // 0..127
    const int cb  = tid & 1;           // which 16B chunk of the k16 slice
    const size_t ga = (size_t)(am0+row)*ldk + k0 + cb*8;
    const size_t gb = (size_t)(bn0+row)*ldk + k0 + cb*8;
    cp16(st +          SWZ64(row, cb),     Ah + ga);   // A hi -> chunks 0..1
    cp16(st +          SWZ64(row, 2 + cb), Al + ga);   // A lo -> chunks 2..3
    cp16(st + SB_OFF + SWZ64(row, cb),     Bh + gb);
    cp16(st + SB_OFF + SWZ64(row, 2 + cb), Bl + gb);
}

__global__ void __launch_bounds__(256, 2) gemm_mma(
    const __nv_bfloat16* __restrict__ Ah, const __nv_bfloat16* __restrict__ Al,
    const __nv_bfloat16* __restrict__ Bh, const __nv_bfloat16* __restrict__ Bl,
    float* __restrict__ C, int K, int ldc,
    const int* __restrict__ tile_expert, int bNrows)
{
    __shared__ char smem[3*STG16];     // 49152 bytes (static limit, 3 stages)
    const uint32_t sb = smem_to_u32(smem);

    int e = 0;
    if (tile_expert) { e = tile_expert[blockIdx.y]; if (e < 0) return; }
    const int m0 = blockIdx.y * 128;
    const int n0 = blockIdx.x * 128;
    const int brow0 = e * bNrows + n0;

    const int tid = threadIdx.x, lane = tid & 31, wid = tid >> 5;
    const int wm = wid & 1, wn = wid >> 1;        // 2 M x 4 N warps, warp tile 64x32

    const int nk = K / 16;

    // prologue: stages 0, 1
    load_stage(sb,         Ah, Al, Bh, Bl, m0, brow0, K, 0,  tid);
    asm volatile("cp.async.commit_group;\n");
    load_stage(sb + STG16, Ah, Al, Bh, Bl, m0, brow0, K, 16, tid);
    asm volatile("cp.async.commit_group;\n");

    float acc[4][4][4];
    #pragma unroll
    for (int a = 0; a < 4; a++)
        #pragma unroll
        for (int b = 0; b < 4; b++)
            #pragma unroll
            for (int c = 0; c < 4; c++) acc[a][b][c] = 0.f;

    int s = 0;   // stage index of iteration kt
    for (int kt = 0; kt < nk; kt++) {
        asm volatile("cp.async.wait_group 1;\n");
        __syncthreads();

        // prefetch stage kt+2 (buffer (kt+2)%3 — its previous contents were
        // consumed at iteration kt-1; the barrier above makes that safe)
        {
            int s2 = s + 2; if (s2 >= 3) s2 -= 3;
            if (kt + 2 < nk)
                load_stage(sb + s2*STG16, Ah, Al, Bh, Bl, m0, brow0, K, (kt+2)*16, tid);
            asm volatile("cp.async.commit_group;\n");
        }

        const uint32_t Ab = sb + s*STG16;

        // B fragments (hi/lo) for this warp's 32 columns
        uint32_t fbh[2][4], fbl[2][4];
        #pragma unroll
        for (int np = 0; np < 2; np++) {
            const int rb = wn*32 + np*16 + (lane & 7) + ((lane >> 4) << 3);
            const int cbh = (lane >> 3) & 1;
            ldm4(fbh[np], Ab + SB_OFF + SWZ64(rb, cbh));
            ldm4(fbl[np], Ab + SB_OFF + SWZ64(rb, 2 + cbh));
        }

        #pragma unroll
        for (int mt = 0; mt < 4; mt++) {
            uint32_t fah[4], fal[4];
            const int ra = wm*64 + mt*16 + (lane & 15);
            const int ca = lane >> 4;
            ldm4(fah, Ab + SWZ64(ra, ca));
            ldm4(fal, Ab + SWZ64(ra, 2 + ca));
            #pragma unroll
            for (int nt = 0; nt < 4; nt++) {
                const int np = nt >> 1, hx = (nt & 1)*2;
                mma16816(acc[mt][nt], fah, fbh[np][hx], fbh[np][hx+1]);
                mma16816(acc[mt][nt], fah, fbl[np][hx], fbl[np][hx+1]);
                mma16816(acc[mt][nt], fal, fbh[np][hx], fbh[np][hx+1]);
            }
        }

        if (++s >= 3) s -= 3;
    }

    // epilogue
    const int rbase = m0 + wm*64 + (lane >> 2);
    const int cbase = n0 + wn*32 + (lane & 3)*2;
    #pragma unroll
    for (int mt = 0; mt < 4; mt++)
        #pragma unroll
        for (int nt = 0; nt < 4; nt++) {
            const long long r0 = rbase + mt*16;
            const int c0 = cbase + nt*8;
            *reinterpret_cast<float2*>(C + r0*ldc + c0) =
                make_float2(acc[mt][nt][0], acc[mt][nt][1]);
            *reinterpret_cast<float2*>(C + (r0+8)*ldc + c0) =
                make_float2(acc[mt][nt][2], acc[mt][nt][3]);
        }
}

// ======================= combine =======================
__global__ void combine_kernel(float* __restrict__ out)
{
    const int t = blockIdx.x;
    __shared__ int   spos[TOPK];
    __shared__ float sw[TOPK];
    if (threadIdx.x < TOPK) {
        spos[threadIdx.x] = g_posmap[t*TOPK + threadIdx.x];
        sw[threadIdx.x]   = g_topw [t*TOPK + threadIdx.x];
    }
    __syncthreads();
    for (int d = threadIdx.x*4; d < DIM; d += blockDim.x*4) {
        float4 a = ld4(out + (long long)t*DIM + d);
        #pragma unroll
        for (int k = 0; k < TOPK; k++) {
            const float4 ev = ld4(g_eout + (long long)spos[k]*DIM + d);
            const float wk = sw[k];
            a.x = fmaf(wk, ev.x, a.x); a.y = fmaf(wk, ev.y, a.y);
            a.z = fmaf(wk, ev.z, a.z); a.w = fmaf(wk, ev.w, a.w);
        }
        *reinterpret_cast<float4*>(out + (long long)t*DIM + d) = a;
    }
}

// ======================= host =======================
extern "C" void kernel_launch(void* const* d_in, const int* in_sizes, int n_in,
                              void* d_out, int out_size)
{
    const float* x    = (const float*)d_in[0];
    const float* gw   = (const float*)d_in[1];
    const float* gb   = (const float*)d_in[2];
    const float* wgu  = (const float*)d_in[3];
    const float* wd   = (const float*)d_in[4];
    const float* wsgu = (const float*)d_in[5];
    const float* wsd  = (const float*)d_in[6];
    float* out = (float*)d_out;

    void *xh, *xl, *agh, *agl, *wguTh, *wguTl, *wdTh, *wdTl,
         *wsguTh, *wsguTl, *wsdTh, *wsdTl, *gu, *gus, *hbh, *hbl,
         *hshh, *hshl, *eout, *tilee;
    cudaGetSymbolAddress(&xh, g_xh);       cudaGetSymbolAddress(&xl, g_xl);
    cudaGetSymbolAddress(&agh, g_agh);     cudaGetSymbolAddress(&agl, g_agl);
    cudaGetSymbolAddress(&wguTh, g_wguT_h);cudaGetSymbolAddress(&wguTl, g_wguT_l);
    cudaGetSymbolAddress(&wdTh, g_wdT_h);  cudaGetSymbolAddress(&wdTl, g_wdT_l);
    cudaGetSymbolAddress(&wsguTh, g_wsguT_h); cudaGetSymbolAddress(&wsguTl, g_wsguT_l);
    cudaGetSymbolAddress(&wsdTh, g_wsdT_h);   cudaGetSymbolAddress(&wsdTl, g_wsdT_l);
    cudaGetSymbolAddress(&gu, g_gu);       cudaGetSymbolAddress(&gus, g_gus);
    cudaGetSymbolAddress(&hbh, g_hbh);     cudaGetSymbolAddress(&hbl, g_hbl);
    cudaGetSymbolAddress(&hshh, g_hsh_h);  cudaGetSymbolAddress(&hshl, g_hsh_l);
    cudaGetSymbolAddress(&eout, g_eout);
    cudaGetSymbolAddress(&tilee, g_tile_expert);

    // --- routing ---
    zero_meta<<<1, 32>>>();
    router_kernel<<<T_TOK, 512>>>(x, gw, gb);
    sched_kernel<<<1, 256>>>();
    scatter_kernel<<<(T_TOK*TOPK + 255)/256, 256>>>();

    // --- conversions ---
    convert_x_kernel<<<(T_TOK*DIM/4 + 255)/256, 256>>>(
        x, (__nv_bfloat16*)xh, (__nv_bfloat16*)xl, (long long)T_TOK*DIM/4);
    gather_rows<<<MAXROWS, 256>>>((const __nv_bfloat16*)xh, (const __nv_bfloat16*)xl,
                                  (__nv_bfloat16*)agh, (__nv_bfloat16*)agl);
    transpose_convert<<<dim3(2*IDIM/32, DIM/32, NEXP), dim3(32,8)>>>(
        wgu, (__nv_bfloat16*)wguTh, (__nv_bfloat16*)wguTl, DIM, 2*IDIM);
    transpose_convert<<<dim3(DIM/32, IDIM/32, NEXP), dim3(32,8)>>>(
        wd, (__nv_bfloat16*)wdTh, (__nv_bfloat16*)wdTl, IDIM, DIM);
    transpose_convert<<<dim3(2*SIDIM/32, DIM/32, 1), dim3(32,8)>>>(
        wsgu, (__nv_bfloat16*)wsguTh, (__nv_bfloat16*)wsguTl, DIM, 2*SIDIM);
    transpose_convert<<<dim3(DIM/32, SIDIM/32, 1), dim3(32,8)>>>(
        wsd, (__nv_bfloat16*)wsdTh, (__nv_bfloat16*)wsdTl, SIDIM, DIM);

    // --- routed expert GEMMs ---
    gemm_mma<<<dim3(2*IDIM/128, MAXTILES), 256>>>(
        (const __nv_bfloat16*)agh, (const __nv_bfloat16*)agl,
        (const __nv_bfloat16*)wguTh, (const __nv_bfloat16*)wguTl,
        (float*)gu, DIM, 2*IDIM, (const int*)tilee, 2*IDIM);
    swiglu_convert<<<((long long)MAXROWS*IDIM/4 + 255)/256, 256>>>(
        (const float*)gu, (__nv_bfloat16*)hbh, (__nv_bfloat16*)hbl,
        IDIM, (long long)MAXROWS*IDIM/4);
    gemm_mma<<<dim3(DIM/128, MAXTILES), 256>>>(
        (const __nv_bfloat16*)hbh, (const __nv_bfloat16*)hbl,
        (const __nv_bfloat16*)wdTh, (const __nv_bfloat16*)wdTl,
        (float*)eout, IDIM, DIM, (const int*)tilee, DIM);

    // --- shared expert GEMMs ---
    gemm_mma<<<dim3(2*SIDIM/128, T_TOK/128), 256>>>(
        (const __nv_bfloat16*)xh, (const __nv_bfloat16*)xl,
        (const __nv_bfloat16*)wsguTh, (const __nv_bfloat16*)wsguTl,
        (float*)gus, DIM, 2*SIDIM, nullptr, 0);
    swiglu_convert<<<((long long)T_TOK*SIDIM/4 + 255)/256, 256>>>(
        (const float*)gus, (__nv_bfloat16*)hshh, (__nv_bfloat16*)hshl,
        SIDIM, (long long)T_TOK*SIDIM/4);
    gemm_mma<<<dim3(DIM/128, T_TOK/128), 256>>>(
        (const __nv_bfloat16*)hshh, (const __nv_bfloat16*)hshl,
        (const __nv_bfloat16*)wsdTh, (const __nv_bfloat16*)wsdTl,
        out, SIDIM, DIM, nullptr, 0);

    // --- combine ---
    combine_kernel<<<T_TOK, 256>>>(out);
}